// round 1
// baseline (speedup 1.0000x reference)
#include <cuda_runtime.h>
#include <math.h>

// ---------------- problem constants ----------------
#define BATCH   4
#define SEQ     4096
#define DMODEL  1024
#define DSTATE  16
#define DCONV   4
#define NHEADS  8
#define CHUNKL  64
#define DINNER  2048
#define HEADDIM 256
#define CONVDIM 2080              // DINNER + 2*DSTATE
#define DPROJ   4136              // 2*DINNER + 2*DSTATE + NHEADS
#define NROWS   (BATCH*SEQ)       // 16384
#define NCHUNK  (SEQ/CHUNKL)      // 64

// ---------------- scratch (static device globals; no cudaMalloc) ----------------
__device__ float g_z     [NROWS*(size_t)DINNER];
__device__ float g_xBC   [NROWS*(size_t)CONVDIM];
__device__ float g_dt    [NROWS*(size_t)NHEADS];
__device__ float g_xh    [NROWS*(size_t)DINNER];
__device__ float g_Bm    [NROWS*(size_t)DSTATE];
__device__ float g_Cm    [NROWS*(size_t)DSTATE];
__device__ float g_states[(size_t)BATCH*NCHUNK*NHEADS*HEADDIM*DSTATE];
__device__ float g_Pst   [(size_t)BATCH*NCHUNK*NHEADS*HEADDIM*DSTATE];
__device__ float g_Y     [NROWS*(size_t)DINNER];

__device__ __forceinline__ float softplus_f(float x) {
    return (x > 20.f) ? x : log1pf(expf(x));
}
__device__ __forceinline__ float silu_f(float x) {
    return x / (1.f + expf(-x));
}

// ============================================================================
// SGEMM (NT): C[M,N] = A[M,K] * B[N,K]^T, both row-major, K contiguous.
// 128x128 tile, BK=16, 256 threads, 8x8 per thread.
// MODE 0: in-proj epilogue (split -> g_z / g_xBC / softplus dt -> g_dt)
// MODE 1: plain store to out, A is taken from g_Y.
// ============================================================================
template<int MODE>
__global__ __launch_bounds__(256, 2)
void sgemm_nt(const float* __restrict__ Ain, const float* __restrict__ Bw,
              int M, int N, int K,
              float* __restrict__ out, const float* __restrict__ dt_bias)
{
    const float* A = (MODE == 1) ? (const float*)g_Y : Ain;

    __shared__ float As[16][128];
    __shared__ float Bs[16][128];

    const int tid = threadIdx.x;
    const int row0 = blockIdx.y * 128;
    const int col0 = blockIdx.x * 128;
    const int ty = tid >> 4;          // 0..15 (M direction)
    const int tx = tid & 15;          // 0..15 (N direction)

    float acc[8][8];
    #pragma unroll
    for (int i = 0; i < 8; i++)
        #pragma unroll
        for (int j = 0; j < 8; j++) acc[i][j] = 0.f;

    const int lr = tid >> 2;          // 0..63
    const int lc = (tid & 3) * 4;     // 0,4,8,12

    for (int k0 = 0; k0 < K; k0 += 16) {
        #pragma unroll
        for (int u = 0; u < 2; u++) {
            int r = lr + u * 64;
            float4 v = *reinterpret_cast<const float4*>(
                &A[(size_t)(row0 + r) * K + k0 + lc]);
            As[lc + 0][r] = v.x; As[lc + 1][r] = v.y;
            As[lc + 2][r] = v.z; As[lc + 3][r] = v.w;
        }
        #pragma unroll
        for (int u = 0; u < 2; u++) {
            int r = lr + u * 64;
            float4 v = make_float4(0.f, 0.f, 0.f, 0.f);
            if (col0 + r < N)
                v = *reinterpret_cast<const float4*>(
                    &Bw[(size_t)(col0 + r) * K + k0 + lc]);
            Bs[lc + 0][r] = v.x; Bs[lc + 1][r] = v.y;
            Bs[lc + 2][r] = v.z; Bs[lc + 3][r] = v.w;
        }
        __syncthreads();

        #pragma unroll
        for (int k = 0; k < 16; k++) {
            float ar[8], br[8];
            float4 a0 = *reinterpret_cast<const float4*>(&As[k][ty * 8]);
            float4 a1 = *reinterpret_cast<const float4*>(&As[k][ty * 8 + 4]);
            float4 b0 = *reinterpret_cast<const float4*>(&Bs[k][tx * 8]);
            float4 b1 = *reinterpret_cast<const float4*>(&Bs[k][tx * 8 + 4]);
            ar[0]=a0.x; ar[1]=a0.y; ar[2]=a0.z; ar[3]=a0.w;
            ar[4]=a1.x; ar[5]=a1.y; ar[6]=a1.z; ar[7]=a1.w;
            br[0]=b0.x; br[1]=b0.y; br[2]=b0.z; br[3]=b0.w;
            br[4]=b1.x; br[5]=b1.y; br[6]=b1.z; br[7]=b1.w;
            #pragma unroll
            for (int i = 0; i < 8; i++)
                #pragma unroll
                for (int j = 0; j < 8; j++)
                    acc[i][j] += ar[i] * br[j];
        }
        __syncthreads();
    }

    const int m0 = row0 + ty * 8;
    const int n0 = col0 + tx * 8;
    #pragma unroll
    for (int i = 0; i < 8; i++) {
        int m = m0 + i;
        #pragma unroll
        for (int j = 0; j < 8; j++) {
            int n = n0 + j;
            if (n >= N) continue;
            float v = acc[i][j];
            if (MODE == 1) {
                out[(size_t)m * N + n] = v;
            } else {
                if (n < DINNER) {
                    g_z[(size_t)m * DINNER + n] = v;
                } else if (n < DINNER + CONVDIM) {
                    g_xBC[(size_t)m * CONVDIM + (n - DINNER)] = v;
                } else {
                    int h = n - (DINNER + CONVDIM);
                    g_dt[(size_t)m * NHEADS + h] = softplus_f(v + dt_bias[h]);
                }
            }
        }
    }
}

// ============================================================================
// Causal depthwise conv (window 4) + bias + SiLU; split into xh (= x*dt), B, C
// ============================================================================
__global__ void conv_silu_kernel(const float* __restrict__ conv_w,
                                 const float* __restrict__ conv_b)
{
    const int row = blockIdx.x;          // b*SEQ + l
    const int b = row / SEQ;
    const int l = row - b * SEQ;
    for (int ch = threadIdx.x; ch < CONVDIM; ch += blockDim.x) {
        float acc = conv_b[ch];
        #pragma unroll
        for (int j = 0; j < DCONV; j++) {
            int ls = l - (DCONV - 1) + j;
            if (ls >= 0)
                acc += conv_w[ch * DCONV + j] *
                       g_xBC[(size_t)(b * SEQ + ls) * CONVDIM + ch];
        }
        float v = silu_f(acc);
        if (ch < DINNER) {
            int h = ch >> 8;
            g_xh[(size_t)row * DINNER + ch] = v * g_dt[(size_t)row * NHEADS + h];
        } else if (ch < DINNER + DSTATE) {
            g_Bm[(size_t)row * DSTATE + (ch - DINNER)] = v;
        } else {
            g_Cm[(size_t)row * DSTATE + (ch - DINNER - DSTATE)] = v;
        }
    }
}

// ============================================================================
// Per-chunk states: states[b,c,h,p,n] = sum_s B[s,n] * exp(a*(63-s)) * xh[s,p]
// One block per (b,c,h); 256 threads = p.
// ============================================================================
__global__ void chunk_states_kernel(const float* __restrict__ log_A)
{
    const int id = blockIdx.x;                 // (b*NCHUNK + c)*NHEADS + h
    const int b = id >> 9;
    const int rem = id & 511;
    const int c = rem >> 3;
    const int h = rem & 7;
    const float a = -expf(log_A[h]);

    __shared__ float Bs[CHUNKL][DSTATE];
    const int t = threadIdx.x;
    for (int i = t; i < CHUNKL * DSTATE; i += 256)
        Bs[i >> 4][i & 15] =
            g_Bm[(size_t)(b * SEQ + c * CHUNKL + (i >> 4)) * DSTATE + (i & 15)];
    __syncthreads();

    float acc[DSTATE];
    #pragma unroll
    for (int n = 0; n < DSTATE; n++) acc[n] = 0.f;

    const int p = t;
    for (int s = 0; s < CHUNKL; s++) {
        float xv = g_xh[(size_t)(b * SEQ + c * CHUNKL + s) * DINNER + h * HEADDIM + p];
        float w = expf(a * (float)(CHUNKL - 1 - s)) * xv;
        #pragma unroll
        for (int n = 0; n < DSTATE; n++) acc[n] += Bs[s][n] * w;
    }
    size_t base = ((size_t)id * HEADDIM + p) * DSTATE;
    #pragma unroll
    for (int n = 0; n < DSTATE; n++) g_states[base + n] = acc[n];
}

// ============================================================================
// Inter-chunk scan: P_c = exp(64a)*P_{c-1} + states_{c-1},  P_0 = 0.
// g_Pst[b,c,...] = state entering chunk c.
// One thread per (b,h,p,n) = 131072 threads.
// ============================================================================
__global__ void state_scan_kernel(const float* __restrict__ log_A)
{
    const int gid = blockIdx.x * blockDim.x + threadIdx.x;
    const int b = gid >> 15;
    const int r = gid & 32767;                 // h*4096 + p*16 + n
    const int h = r >> 12;
    const float a = -expf(log_A[h]);
    const float d = expf(a * (float)CHUNKL);
    float P = 0.f;
    for (int c = 0; c < NCHUNK; c++) {
        size_t off = (size_t)(b * NCHUNK + c) * 32768 + r;
        g_Pst[off] = P;
        P = d * P + g_states[off];
    }
}

// ============================================================================
// Y kernel: per (b,c,h) block computes Y[64,256] =
//   (C B^T ∘ decay) @ xh   +  exp(a(t+1)) * (C @ P^T)  +  D_skip * xh
// Dynamic smem: Bs(1024) Cs(1024) G(4096) xs(16384) floats = 88 KiB.
// ============================================================================
__global__ void ssd_y_kernel(const float* __restrict__ log_A,
                             const float* __restrict__ D_skip)
{
    extern __shared__ float sh[];
    float* Bs = sh;                  // 64*16
    float* Cs = sh + 1024;           // 64*16
    float* G  = sh + 2048;           // 64*64
    float* xs = sh + 2048 + 4096;    // 64*256

    const int id = blockIdx.x;
    const int b = id >> 9;
    const int rem = id & 511;
    const int c = rem >> 3;
    const int h = rem & 7;
    const float a = -expf(log_A[h]);
    const int t = threadIdx.x;
    const int rowbase = b * SEQ + c * CHUNKL;

    for (int i = t; i < CHUNKL * DSTATE; i += 256) {
        size_t gi = (size_t)(rowbase + (i >> 4)) * DSTATE + (i & 15);
        Bs[i] = g_Bm[gi];
        Cs[i] = g_Cm[gi];
    }
    for (int i = t; i < CHUNKL * HEADDIM; i += 256) {
        int s = i >> 8, p = i & 255;
        xs[i] = g_xh[(size_t)(rowbase + s) * DINNER + h * HEADDIM + p];
    }
    __syncthreads();

    // G[t,s] = exp(a(t-s)) * (C_t . B_s) for s<=t, else 0
    for (int e = t * 16; e < t * 16 + 16; e++) {
        int tt = e >> 6, ss = e & 63;
        float val = 0.f;
        if (ss <= tt) {
            float dot = 0.f;
            #pragma unroll
            for (int n = 0; n < DSTATE; n++) dot += Cs[tt * 16 + n] * Bs[ss * 16 + n];
            val = expf(a * (float)(tt - ss)) * dot;
        }
        G[e] = val;
    }
    __syncthreads();

    const int p = t;
    float Preg[DSTATE];
    size_t pbase = ((size_t)id * HEADDIM + p) * DSTATE;
    #pragma unroll
    for (int n = 0; n < DSTATE; n++) Preg[n] = g_Pst[pbase + n];
    const float dsk = D_skip[h];

    for (int tt = 0; tt < CHUNKL; tt++) {
        float acc = 0.f;
        const float* Gr = &G[tt * 64];
        for (int ss = 0; ss <= tt; ss++) acc += Gr[ss] * xs[ss * 256 + p];
        float offv = 0.f;
        #pragma unroll
        for (int n = 0; n < DSTATE; n++) offv += Cs[tt * 16 + n] * Preg[n];
        float y = acc + expf(a * (float)(tt + 1)) * offv + dsk * xs[tt * 256 + p];
        g_Y[(size_t)(rowbase + tt) * DINNER + h * HEADDIM + p] = y;
    }
}

// ============================================================================
// Gate with silu(z), RMS-norm over 2048, scale by norm_w. In-place on g_Y.
// ============================================================================
__global__ void rms_gate_kernel(const float* __restrict__ norm_w)
{
    const int row = blockIdx.x;
    const int t = threadIdx.x;
    float v[8];
    float ss = 0.f;
    #pragma unroll
    for (int k = 0; k < 8; k++) {
        int ch = k * 256 + t;
        float Yv = g_Y[(size_t)row * DINNER + ch];
        float zv = g_z[(size_t)row * DINNER + ch];
        float val = Yv * silu_f(zv);
        v[k] = val;
        ss += val * val;
    }
    __shared__ float red[256];
    red[t] = ss;
    __syncthreads();
    for (int st = 128; st > 0; st >>= 1) {
        if (t < st) red[t] += red[t + st];
        __syncthreads();
    }
    float inv = rsqrtf(red[0] / (float)DINNER + 1e-5f);
    #pragma unroll
    for (int k = 0; k < 8; k++) {
        int ch = k * 256 + t;
        g_Y[(size_t)row * DINNER + ch] = v[k] * inv * norm_w[ch];
    }
}

// ============================================================================
// Launch
// ============================================================================
extern "C" void kernel_launch(void* const* d_in, const int* in_sizes, int n_in,
                              void* d_out, int out_size)
{
    const float* input   = (const float*)d_in[0];   // [4,4096,1024]
    const float* W_in    = (const float*)d_in[1];   // [4136,1024]
    const float* conv_w  = (const float*)d_in[2];   // [2080,1,4]
    const float* conv_b  = (const float*)d_in[3];   // [2080]
    const float* dt_bias = (const float*)d_in[4];   // [8]
    const float* log_A   = (const float*)d_in[5];   // [8]
    const float* D_skip  = (const float*)d_in[6];   // [8]
    const float* norm_w  = (const float*)d_in[7];   // [2048]
    const float* W_out   = (const float*)d_in[8];   // [1024,2048]
    float* out = (float*)d_out;                     // [4,4096,1024] f32

    (void)in_sizes; (void)n_in; (void)out_size;

    const int SMEM_Y = (1024 + 1024 + 4096 + 16384) * 4;   // 90112 B
    cudaFuncSetAttribute(ssd_y_kernel,
                         cudaFuncAttributeMaxDynamicSharedMemorySize, SMEM_Y);

    dim3 blk(256);

    // 1) in-projection + split + softplus(dt)
    sgemm_nt<0><<<dim3((DPROJ + 127) / 128, NROWS / 128), blk>>>(
        input, W_in, NROWS, DPROJ, DMODEL, nullptr, dt_bias);

    // 2) depthwise conv + silu + split (xh = x*dt, B, C)
    conv_silu_kernel<<<NROWS, 256>>>(conv_w, conv_b);

    // 3) per-chunk states
    chunk_states_kernel<<<BATCH * NCHUNK * NHEADS, 256>>>(log_A);

    // 4) inter-chunk scan
    state_scan_kernel<<<(BATCH * NHEADS * HEADDIM * DSTATE) / 256, 256>>>(log_A);

    // 5) Y = diag + off + skip
    ssd_y_kernel<<<BATCH * NCHUNK * NHEADS, 256, SMEM_Y>>>(log_A, D_skip);

    // 6) gate + RMS norm (in-place on g_Y)
    rms_gate_kernel<<<NROWS, 256>>>(norm_w);

    // 7) out-projection
    sgemm_nt<1><<<dim3(DMODEL / 128, NROWS / 128), blk>>>(
        nullptr, W_out, NROWS, DMODEL, DINNER, out, nullptr);
}

// round 6
// speedup vs baseline: 3.7834x; 3.7834x over previous
#include <cuda_runtime.h>
#include <cuda_bf16.h>
#include <math.h>
#include <stdint.h>

// ---------------- problem constants ----------------
#define BATCH   4
#define SEQ     4096
#define DMODEL  1024
#define DSTATE  16
#define DCONV   4
#define NHEADS  8
#define CHUNKL  64
#define DINNER  2048
#define HEADDIM 256
#define CONVDIM 2080              // DINNER + 2*DSTATE
#define DPROJ   4136              // 2*DINNER + 2*DSTATE + NHEADS
#define NROWS   (BATCH*SEQ)       // 16384
#define NCHUNK  (SEQ/CHUNKL)      // 64
#define NPAD1   4224              // 33*128 padded N for GEMM1

// ---------------- scratch (static device globals) ----------------
__device__ float g_z     [NROWS*(size_t)DINNER];
__device__ float g_xBC   [NROWS*(size_t)CONVDIM];
__device__ float g_dt    [NROWS*(size_t)NHEADS];
__device__ float g_xh    [NROWS*(size_t)DINNER];
__device__ float g_Bm    [NROWS*(size_t)DSTATE];
__device__ float g_Cm    [NROWS*(size_t)DSTATE];
__device__ float g_states[(size_t)BATCH*NCHUNK*NHEADS*HEADDIM*DSTATE];
__device__ float g_Pst   [(size_t)BATCH*NCHUNK*NHEADS*HEADDIM*DSTATE];
__device__ float g_Y     [NROWS*(size_t)DINNER];

// bf16 hi/lo split buffers
__device__ __nv_bfloat16 g_Xhi [NROWS*(size_t)DMODEL];
__device__ __nv_bfloat16 g_Xlo [NROWS*(size_t)DMODEL];
__device__ __nv_bfloat16 g_W1hi[(size_t)NPAD1*DMODEL];
__device__ __nv_bfloat16 g_W1lo[(size_t)NPAD1*DMODEL];
__device__ __nv_bfloat16 g_W2hi[(size_t)DMODEL*DINNER];
__device__ __nv_bfloat16 g_W2lo[(size_t)DMODEL*DINNER];
__device__ __nv_bfloat16 g_Yhi [NROWS*(size_t)DINNER];
__device__ __nv_bfloat16 g_Ylo [NROWS*(size_t)DINNER];

__device__ __forceinline__ float softplus_f(float x) {
    return (x > 20.f) ? x : log1pf(expf(x));
}
__device__ __forceinline__ float silu_f(float x) {
    return x / (1.f + expf(-x));
}

__device__ __forceinline__ uint32_t smem_u32(const void* p) {
    uint32_t a;
    asm("{ .reg .u64 t; cvta.to.shared.u64 t, %1; cvt.u32.u64 %0, t; }"
        : "=r"(a) : "l"(p));
    return a;
}

#define CP_COMMIT() asm volatile("cp.async.commit_group;" ::: "memory")
#define CP_WAIT1()  asm volatile("cp.async.wait_group 1;" ::: "memory")

__device__ __forceinline__ void ldmat_x4(uint32_t a, uint32_t& r0, uint32_t& r1,
                                         uint32_t& r2, uint32_t& r3) {
    asm volatile("ldmatrix.sync.aligned.m8n8.x4.shared.b16 {%0,%1,%2,%3}, [%4];"
                 : "=r"(r0), "=r"(r1), "=r"(r2), "=r"(r3) : "r"(a));
}
__device__ __forceinline__ void mma_bf16(float* c, uint32_t a0, uint32_t a1,
                                         uint32_t a2, uint32_t a3,
                                         uint32_t b0, uint32_t b1) {
    asm volatile(
        "mma.sync.aligned.m16n8k16.row.col.f32.bf16.bf16.f32 "
        "{%0,%1,%2,%3}, {%4,%5,%6,%7}, {%8,%9}, {%0,%1,%2,%3};"
        : "+f"(c[0]), "+f"(c[1]), "+f"(c[2]), "+f"(c[3])
        : "r"(a0), "r"(a1), "r"(a2), "r"(a3), "r"(b0), "r"(b1));
}

// copy one 128x64-bf16 tile (128B rows, SW128 swizzle) global->smem via cp.async
__device__ __forceinline__ void load_tile(uint32_t sbase, const __nv_bfloat16* g,
                                          int rowbase, int K, int k0, int tid) {
    #pragma unroll
    for (int it = 0; it < 4; it++) {
        int chunk = tid + it * 256;          // 0..1023 : 16B units
        int row = chunk >> 3;
        int c16 = chunk & 7;
        uint32_t soff = (uint32_t)(row * 128 + c16 * 16);
        soff ^= ((soff >> 3) & 0x70);        // SW128
        const void* gp = g + (size_t)(rowbase + row) * K + k0 + c16 * 8;
        asm volatile("cp.async.cg.shared.global [%0], [%1], 16;"
                     :: "r"(sbase + soff), "l"(gp) : "memory");
    }
}

// swizzled shared address within a 128x64-bf16 tile
__device__ __forceinline__ uint32_t tile_addr(uint32_t base, int row, int colb) {
    uint32_t off = (uint32_t)(row * 128 + colb);
    off ^= ((off >> 3) & 0x70);
    return base + off;
}

// ============================================================================
// mma.sync bf16 GEMM (NT): C[M,Npad] = A[M,K] * B[Npad,K]^T, hi/lo split, f32 acc
// tile 128x128, K-chunk 64, 3-stage cp.async pipeline, 256 threads (8 warps 2x4).
// MODE 0: in-proj epilogue (split -> g_z / g_xBC / softplus dt)
// MODE 1: plain f32 store to out [M x 1024]
// ============================================================================
#define STAGE_BYTES 65536        // 4 tiles x 16KB (Ahi Alo Bhi Blo)

template<int MODE>
__global__ __launch_bounds__(256, 1)
void mma_gemm(const __nv_bfloat16* __restrict__ Ahi, const __nv_bfloat16* __restrict__ Alo,
              const __nv_bfloat16* __restrict__ Bhi, const __nv_bfloat16* __restrict__ Blo,
              int K, float* __restrict__ out, const float* __restrict__ dt_bias)
{
    extern __shared__ char smem[];
    const uint32_t sb = smem_u32(smem);
    const int tid = threadIdx.x;
    const int wid = tid >> 5;
    const int lane = tid & 31;
    const int row0 = blockIdx.y * 128;
    const int col0 = blockIdx.x * 128;
    const int NC = K / 64;

    const int wm = wid >> 2;          // 0..1 : warp row   (64 rows)
    const int wn = wid & 3;           // 0..3 : warp col   (32 cols)

    float acc[4][4][4];               // [mt][nj][reg]
    #pragma unroll
    for (int i = 0; i < 4; i++)
        #pragma unroll
        for (int j = 0; j < 4; j++)
            #pragma unroll
            for (int r = 0; r < 4; r++) acc[i][j][r] = 0.f;

    // ldmatrix lane addressing
    const int grp = lane >> 3;        // 0..3
    const int wit = lane & 7;         // 0..7
    // A pattern: rows wit + (grp&1)*8, col bytes (grp>>1)*16
    const int a_r = wit + (grp & 1) * 8;
    const int a_c = (grp >> 1) * 16;
    // B pattern: rows wit + (grp>>1)*8, col bytes (grp&1)*16
    const int b_r = wit + (grp >> 1) * 8;
    const int b_c = (grp & 1) * 16;

    // prologue: stages 0,1
    #pragma unroll
    for (int i = 0; i < 2; i++) {
        uint32_t stb = sb + i * STAGE_BYTES;
        load_tile(stb,         Ahi, row0, K, i * 64, tid);
        load_tile(stb + 16384, Alo, row0, K, i * 64, tid);
        load_tile(stb + 32768, Bhi, col0, K, i * 64, tid);
        load_tile(stb + 49152, Blo, col0, K, i * 64, tid);
        CP_COMMIT();
    }

    for (int i = 0; i < NC; i++) {
        const int s = i % 3;
        CP_WAIT1();
        __syncthreads();

        if (i + 2 < NC) {
            int s2 = (i + 2) % 3;
            uint32_t stb = sb + s2 * STAGE_BYTES;
            load_tile(stb,         Ahi, row0, K, (i + 2) * 64, tid);
            load_tile(stb + 16384, Alo, row0, K, (i + 2) * 64, tid);
            load_tile(stb + 32768, Bhi, col0, K, (i + 2) * 64, tid);
            load_tile(stb + 49152, Blo, col0, K, (i + 2) * 64, tid);
            CP_COMMIT();
        }

        const uint32_t sAh = sb + s * STAGE_BYTES;
        const uint32_t sAl = sAh + 16384;
        const uint32_t sBh = sAh + 32768;
        const uint32_t sBl = sAh + 49152;

        #pragma unroll
        for (int ks = 0; ks < 4; ks++) {
            const int kb = ks * 32;   // byte offset of this k16 within 128B row

            uint32_t ah[4][4], al[4][4];
            #pragma unroll
            for (int mt = 0; mt < 4; mt++) {
                int r = wm * 64 + mt * 16 + a_r;
                ldmat_x4(tile_addr(sAh, r, kb + a_c),
                         ah[mt][0], ah[mt][1], ah[mt][2], ah[mt][3]);
                ldmat_x4(tile_addr(sAl, r, kb + a_c),
                         al[mt][0], al[mt][1], al[mt][2], al[mt][3]);
            }
            uint32_t bh[4][2], bl[4][2];
            #pragma unroll
            for (int np = 0; np < 2; np++) {   // n-pair: covers n8 tiles 2np, 2np+1
                int r = wn * 32 + np * 16 + b_r;
                uint32_t t0, t1, t2, t3;
                ldmat_x4(tile_addr(sBh, r, kb + b_c), t0, t1, t2, t3);
                bh[2*np][0] = t0; bh[2*np][1] = t1;
                bh[2*np+1][0] = t2; bh[2*np+1][1] = t3;
                ldmat_x4(tile_addr(sBl, r, kb + b_c), t0, t1, t2, t3);
                bl[2*np][0] = t0; bl[2*np][1] = t1;
                bl[2*np+1][0] = t2; bl[2*np+1][1] = t3;
            }

            #pragma unroll
            for (int mt = 0; mt < 4; mt++)
                #pragma unroll
                for (int nj = 0; nj < 4; nj++) {
                    mma_bf16(acc[mt][nj], ah[mt][0], ah[mt][1], ah[mt][2], ah[mt][3],
                             bh[nj][0], bh[nj][1]);
                    mma_bf16(acc[mt][nj], ah[mt][0], ah[mt][1], ah[mt][2], ah[mt][3],
                             bl[nj][0], bl[nj][1]);
                    mma_bf16(acc[mt][nj], al[mt][0], al[mt][1], al[mt][2], al[mt][3],
                             bh[nj][0], bh[nj][1]);
                }
        }
        __syncthreads();
    }

    // epilogue: direct global stores (each 4-lane quad covers a 32B sector)
    #pragma unroll
    for (int mt = 0; mt < 4; mt++) {
        #pragma unroll
        for (int nj = 0; nj < 4; nj++) {
            int m = row0 + wm * 64 + mt * 16 + (lane >> 2);
            int n = col0 + wn * 32 + nj * 8 + (lane & 3) * 2;
            #pragma unroll
            for (int half = 0; half < 2; half++) {
                int mm = m + half * 8;
                float v0 = acc[mt][nj][half * 2 + 0];
                float v1 = acc[mt][nj][half * 2 + 1];
                if (MODE == 1) {
                    out[(size_t)mm * DMODEL + n]     = v0;
                    out[(size_t)mm * DMODEL + n + 1] = v1;
                } else {
                    #pragma unroll
                    for (int e = 0; e < 2; e++) {
                        int nn = n + e;
                        float v = e ? v1 : v0;
                        if (nn < DINNER) {
                            g_z[(size_t)mm * DINNER + nn] = v;
                        } else if (nn < DINNER + CONVDIM) {
                            g_xBC[(size_t)mm * CONVDIM + (nn - DINNER)] = v;
                        } else if (nn < DPROJ) {
                            int h = nn - (DINNER + CONVDIM);
                            g_dt[(size_t)mm * NHEADS + h] =
                                softplus_f(v + dt_bias[h]);
                        }
                    }
                }
            }
        }
    }
}

// ============================================================================
// hi/lo split kernels
// ============================================================================
__global__ void split_plain(const float* __restrict__ src,
                            __nv_bfloat16* __restrict__ hi,
                            __nv_bfloat16* __restrict__ lo, int n)
{
    int i = blockIdx.x * blockDim.x + threadIdx.x;
    if (i >= n) return;
    float x = src[i];
    __nv_bfloat16 h = __float2bfloat16(x);
    hi[i] = h;
    lo[i] = __float2bfloat16(x - __bfloat162float(h));
}

__global__ void split_w1_pad(const float* __restrict__ W)
{
    int i = blockIdx.x * blockDim.x + threadIdx.x;   // over NPAD1*DMODEL
    if (i >= NPAD1 * DMODEL) return;
    int r = i / DMODEL;
    float x = (r < DPROJ) ? W[(size_t)r * DMODEL + (i - r * DMODEL)] : 0.f;
    __nv_bfloat16 h = __float2bfloat16(x);
    g_W1hi[i] = h;
    g_W1lo[i] = __float2bfloat16(x - __bfloat162float(h));
}

// ============================================================================
// Causal depthwise conv + SiLU + split
// ============================================================================
__global__ void conv_silu_kernel(const float* __restrict__ conv_w,
                                 const float* __restrict__ conv_b)
{
    const int row = blockIdx.x;
    const int b = row / SEQ;
    const int l = row - b * SEQ;
    for (int ch = threadIdx.x; ch < CONVDIM; ch += blockDim.x) {
        float acc = conv_b[ch];
        #pragma unroll
        for (int j = 0; j < DCONV; j++) {
            int ls = l - (DCONV - 1) + j;
            if (ls >= 0)
                acc += conv_w[ch * DCONV + j] *
                       g_xBC[(size_t)(b * SEQ + ls) * CONVDIM + ch];
        }
        float v = silu_f(acc);
        if (ch < DINNER) {
            int h = ch >> 8;
            g_xh[(size_t)row * DINNER + ch] = v * g_dt[(size_t)row * NHEADS + h];
        } else if (ch < DINNER + DSTATE) {
            g_Bm[(size_t)row * DSTATE + (ch - DINNER)] = v;
        } else {
            g_Cm[(size_t)row * DSTATE + (ch - DINNER - DSTATE)] = v;
        }
    }
}

// ============================================================================
// Per-chunk states
// ============================================================================
__global__ void chunk_states_kernel(const float* __restrict__ log_A)
{
    const int id = blockIdx.x;
    const int b = id >> 9;
    const int rem = id & 511;
    const int c = rem >> 3;
    const int h = rem & 7;
    const float a = -expf(log_A[h]);

    __shared__ float Bs[CHUNKL][DSTATE];
    const int t = threadIdx.x;
    for (int i = t; i < CHUNKL * DSTATE; i += 256)
        Bs[i >> 4][i & 15] =
            g_Bm[(size_t)(b * SEQ + c * CHUNKL + (i >> 4)) * DSTATE + (i & 15)];
    __syncthreads();

    float acc[DSTATE];
    #pragma unroll
    for (int n = 0; n < DSTATE; n++) acc[n] = 0.f;

    const int p = t;
    for (int s = 0; s < CHUNKL; s++) {
        float xv = g_xh[(size_t)(b * SEQ + c * CHUNKL + s) * DINNER + h * HEADDIM + p];
        float w = expf(a * (float)(CHUNKL - 1 - s)) * xv;
        #pragma unroll
        for (int n = 0; n < DSTATE; n++) acc[n] += Bs[s][n] * w;
    }
    size_t base = ((size_t)id * HEADDIM + p) * DSTATE;
    #pragma unroll
    for (int n = 0; n < DSTATE; n++) g_states[base + n] = acc[n];
}

// ============================================================================
// Inter-chunk scan
// ============================================================================
__global__ void state_scan_kernel(const float* __restrict__ log_A)
{
    const int gid = blockIdx.x * blockDim.x + threadIdx.x;
    const int b = gid >> 15;
    const int r = gid & 32767;
    const int h = r >> 12;
    const float a = -expf(log_A[h]);
    const float d = expf(a * (float)CHUNKL);
    float P = 0.f;
    for (int c = 0; c < NCHUNK; c++) {
        size_t off = (size_t)(b * NCHUNK + c) * 32768 + r;
        g_Pst[off] = P;
        P = d * P + g_states[off];
    }
}

// ============================================================================
// SSD Y kernel
// ============================================================================
__global__ void ssd_y_kernel(const float* __restrict__ log_A,
                             const float* __restrict__ D_skip)
{
    extern __shared__ float sh[];
    float* Bs = sh;
    float* Cs = sh + 1024;
    float* G  = sh + 2048;
    float* xs = sh + 2048 + 4096;

    const int id = blockIdx.x;
    const int b = id >> 9;
    const int rem = id & 511;
    const int c = rem >> 3;
    const int h = rem & 7;
    const float a = -expf(log_A[h]);
    const int t = threadIdx.x;
    const int rowbase = b * SEQ + c * CHUNKL;

    for (int i = t; i < CHUNKL * DSTATE; i += 256) {
        size_t gi = (size_t)(rowbase + (i >> 4)) * DSTATE + (i & 15);
        Bs[i] = g_Bm[gi];
        Cs[i] = g_Cm[gi];
    }
    for (int i = t; i < CHUNKL * HEADDIM; i += 256) {
        int s = i >> 8, p = i & 255;
        xs[i] = g_xh[(size_t)(rowbase + s) * DINNER + h * HEADDIM + p];
    }
    __syncthreads();

    for (int e = t * 16; e < t * 16 + 16; e++) {
        int tt = e >> 6, ss = e & 63;
        float val = 0.f;
        if (ss <= tt) {
            float dot = 0.f;
            #pragma unroll
            for (int n = 0; n < DSTATE; n++) dot += Cs[tt * 16 + n] * Bs[ss * 16 + n];
            val = expf(a * (float)(tt - ss)) * dot;
        }
        G[e] = val;
    }
    __syncthreads();

    const int p = t;
    float Preg[DSTATE];
    size_t pbase = ((size_t)id * HEADDIM + p) * DSTATE;
    #pragma unroll
    for (int n = 0; n < DSTATE; n++) Preg[n] = g_Pst[pbase + n];
    const float dsk = D_skip[h];

    for (int tt = 0; tt < CHUNKL; tt++) {
        float acc = 0.f;
        const float* Gr = &G[tt * 64];
        for (int ss = 0; ss <= tt; ss++) acc += Gr[ss] * xs[ss * 256 + p];
        float offv = 0.f;
        #pragma unroll
        for (int n = 0; n < DSTATE; n++) offv += Cs[tt * 16 + n] * Preg[n];
        float y = acc + expf(a * (float)(tt + 1)) * offv + dsk * xs[tt * 256 + p];
        g_Y[(size_t)(rowbase + tt) * DINNER + h * HEADDIM + p] = y;
    }
}

// ============================================================================
// Gate + RMS norm; emits bf16 hi/lo for GEMM2
// ============================================================================
__global__ void rms_gate_kernel(const float* __restrict__ norm_w)
{
    const int row = blockIdx.x;
    const int t = threadIdx.x;
    float v[8];
    float ss = 0.f;
    #pragma unroll
    for (int k = 0; k < 8; k++) {
        int ch = k * 256 + t;
        float Yv = g_Y[(size_t)row * DINNER + ch];
        float zv = g_z[(size_t)row * DINNER + ch];
        float val = Yv * silu_f(zv);
        v[k] = val;
        ss += val * val;
    }
    __shared__ float red[256];
    red[t] = ss;
    __syncthreads();
    for (int st = 128; st > 0; st >>= 1) {
        if (t < st) red[t] += red[t + st];
        __syncthreads();
    }
    float inv = rsqrtf(red[0] / (float)DINNER + 1e-5f);
    #pragma unroll
    for (int k = 0; k < 8; k++) {
        int ch = k * 256 + t;
        float val = v[k] * inv * norm_w[ch];
        __nv_bfloat16 hv = __float2bfloat16(val);
        g_Yhi[(size_t)row * DINNER + ch] = hv;
        g_Ylo[(size_t)row * DINNER + ch] =
            __float2bfloat16(val - __bfloat162float(hv));
    }
}

// ============================================================================
// Launch
// ============================================================================
extern "C" void kernel_launch(void* const* d_in, const int* in_sizes, int n_in,
                              void* d_out, int out_size)
{
    const float* input   = (const float*)d_in[0];
    const float* W_in    = (const float*)d_in[1];
    const float* conv_w  = (const float*)d_in[2];
    const float* conv_b  = (const float*)d_in[3];
    const float* dt_bias = (const float*)d_in[4];
    const float* log_A   = (const float*)d_in[5];
    const float* D_skip  = (const float*)d_in[6];
    const float* norm_w  = (const float*)d_in[7];
    const float* W_out   = (const float*)d_in[8];
    float* out = (float*)d_out;

    (void)in_sizes; (void)n_in; (void)out_size;

    const int GSMEM = 3 * STAGE_BYTES;               // 196608 B
    const int SMEM_Y = (1024 + 1024 + 4096 + 16384) * 4;
    cudaFuncSetAttribute(mma_gemm<0>, cudaFuncAttributeMaxDynamicSharedMemorySize, GSMEM);
    cudaFuncSetAttribute(mma_gemm<1>, cudaFuncAttributeMaxDynamicSharedMemorySize, GSMEM);
    cudaFuncSetAttribute(ssd_y_kernel, cudaFuncAttributeMaxDynamicSharedMemorySize, SMEM_Y);

    __nv_bfloat16 *Xhi, *Xlo, *W2hi, *W2lo, *Yhi, *Ylo, *W1hi, *W1lo;
    cudaGetSymbolAddress((void**)&Xhi,  g_Xhi);
    cudaGetSymbolAddress((void**)&Xlo,  g_Xlo);
    cudaGetSymbolAddress((void**)&W2hi, g_W2hi);
    cudaGetSymbolAddress((void**)&W2lo, g_W2lo);
    cudaGetSymbolAddress((void**)&Yhi,  g_Yhi);
    cudaGetSymbolAddress((void**)&Ylo,  g_Ylo);
    cudaGetSymbolAddress((void**)&W1hi, g_W1hi);
    cudaGetSymbolAddress((void**)&W1lo, g_W1lo);

    // splits
    {
        int n = NROWS * DMODEL;
        split_plain<<<(n + 255) / 256, 256>>>(input, Xhi, Xlo, n);
    }
    split_w1_pad<<<(NPAD1 * DMODEL + 255) / 256, 256>>>(W_in);
    {
        int n = DMODEL * DINNER;
        split_plain<<<(n + 255) / 256, 256>>>(W_out, W2hi, W2lo, n);
    }

    // 1) in-projection (mma.sync bf16 split)
    mma_gemm<0><<<dim3(NPAD1 / 128, NROWS / 128), 256, GSMEM>>>(
        Xhi, Xlo, W1hi, W1lo, DMODEL, nullptr, dt_bias);

    // 2) conv + silu + split
    conv_silu_kernel<<<NROWS, 256>>>(conv_w, conv_b);

    // 3) per-chunk states
    chunk_states_kernel<<<BATCH * NCHUNK * NHEADS, 256>>>(log_A);

    // 4) inter-chunk scan
    state_scan_kernel<<<(BATCH * NHEADS * HEADDIM * DSTATE) / 256, 256>>>(log_A);

    // 5) Y
    ssd_y_kernel<<<BATCH * NCHUNK * NHEADS, 256, SMEM_Y>>>(log_A, D_skip);

    // 6) gate + RMS norm (emits bf16 hi/lo)
    rms_gate_kernel<<<NROWS, 256>>>(norm_w);

    // 7) out-projection (mma.sync bf16 split)
    mma_gemm<1><<<dim3(DMODEL / 128, NROWS / 128), 256, GSMEM>>>(
        Yhi, Ylo, W2hi, W2lo, DINNER, out, nullptr);
}

// round 8
// speedup vs baseline: 3.8267x; 1.0114x over previous
#include <cuda_runtime.h>
#include <cuda_bf16.h>
#include <math.h>
#include <stdint.h>

// ---------------- problem constants ----------------
#define BATCH   4
#define SEQ     4096
#define DMODEL  1024
#define DSTATE  16
#define DCONV   4
#define NHEADS  8
#define CHUNKL  64
#define DINNER  2048
#define HEADDIM 256
#define CONVDIM 2080              // DINNER + 2*DSTATE
#define DPROJ   4136              // 2*DINNER + 2*DSTATE + NHEADS
#define NROWS   (BATCH*SEQ)       // 16384
#define NCHUNK  (SEQ/CHUNKL)      // 64
#define NPAD1   4224              // 33*128 padded N for GEMM1

// ---------------- scratch (static device globals) ----------------
__device__ float g_z     [NROWS*(size_t)DINNER];
__device__ float g_xBC   [NROWS*(size_t)CONVDIM];
__device__ float g_dt    [NROWS*(size_t)NHEADS];
__device__ float g_xh    [NROWS*(size_t)DINNER];
__device__ float g_Bm    [NROWS*(size_t)DSTATE];
__device__ float g_Cm    [NROWS*(size_t)DSTATE];
__device__ float g_states[(size_t)BATCH*NCHUNK*NHEADS*HEADDIM*DSTATE];
__device__ float g_Pst   [(size_t)BATCH*NCHUNK*NHEADS*HEADDIM*DSTATE];
__device__ float g_Y     [NROWS*(size_t)DINNER];

// bf16 hi/lo split buffers
__device__ __nv_bfloat16 g_Xhi [NROWS*(size_t)DMODEL];
__device__ __nv_bfloat16 g_Xlo [NROWS*(size_t)DMODEL];
__device__ __nv_bfloat16 g_W1hi[(size_t)NPAD1*DMODEL];
__device__ __nv_bfloat16 g_W1lo[(size_t)NPAD1*DMODEL];
__device__ __nv_bfloat16 g_W2hi[(size_t)DMODEL*DINNER];
__device__ __nv_bfloat16 g_W2lo[(size_t)DMODEL*DINNER];
__device__ __nv_bfloat16 g_Yhi [NROWS*(size_t)DINNER];
__device__ __nv_bfloat16 g_Ylo [NROWS*(size_t)DINNER];

__device__ __forceinline__ float softplus_f(float x) {
    return (x > 20.f) ? x : log1pf(expf(x));
}
__device__ __forceinline__ float silu_f(float x) {
    return x / (1.f + expf(-x));
}

__device__ __forceinline__ uint32_t smem_u32(const void* p) {
    uint32_t a;
    asm("{ .reg .u64 t; cvta.to.shared.u64 t, %1; cvt.u32.u64 %0, t; }"
        : "=r"(a) : "l"(p));
    return a;
}

#define CP_COMMIT() asm volatile("cp.async.commit_group;" ::: "memory")
#define CP_WAIT1()  asm volatile("cp.async.wait_group 1;" ::: "memory")

__device__ __forceinline__ void ldmat_x4(uint32_t a, uint32_t& r0, uint32_t& r1,
                                         uint32_t& r2, uint32_t& r3) {
    asm volatile("ldmatrix.sync.aligned.m8n8.x4.shared.b16 {%0,%1,%2,%3}, [%4];"
                 : "=r"(r0), "=r"(r1), "=r"(r2), "=r"(r3) : "r"(a));
}
__device__ __forceinline__ void mma_bf16(float* c, uint32_t a0, uint32_t a1,
                                         uint32_t a2, uint32_t a3,
                                         uint32_t b0, uint32_t b1) {
    asm volatile(
        "mma.sync.aligned.m16n8k16.row.col.f32.bf16.bf16.f32 "
        "{%0,%1,%2,%3}, {%4,%5,%6,%7}, {%8,%9}, {%0,%1,%2,%3};"
        : "+f"(c[0]), "+f"(c[1]), "+f"(c[2]), "+f"(c[3])
        : "r"(a0), "r"(a1), "r"(a2), "r"(a3), "r"(b0), "r"(b1));
}

// copy one 128x64-bf16 tile (128B rows, SW128 swizzle) global->smem via cp.async
// 512 threads: 1024 16B-chunks -> 2 per thread
__device__ __forceinline__ void load_tile(uint32_t sbase, const __nv_bfloat16* g,
                                          int rowbase, int K, int k0, int tid) {
    #pragma unroll
    for (int it = 0; it < 2; it++) {
        int chunk = tid + it * 512;          // 0..1023 : 16B units
        int row = chunk >> 3;
        int c16 = chunk & 7;
        uint32_t soff = (uint32_t)(row * 128 + c16 * 16);
        soff ^= ((soff >> 3) & 0x70);        // SW128
        const void* gp = g + (size_t)(rowbase + row) * K + k0 + c16 * 8;
        asm volatile("cp.async.cg.shared.global [%0], [%1], 16;"
                     :: "r"(sbase + soff), "l"(gp) : "memory");
    }
}

// swizzled shared address within a 128x64-bf16 tile
__device__ __forceinline__ uint32_t tile_addr(uint32_t base, int row, int colb) {
    uint32_t off = (uint32_t)(row * 128 + colb);
    off ^= ((off >> 3) & 0x70);
    return base + off;
}

// ============================================================================
// mma.sync bf16 GEMM (NT): C[M,Npad] = A[M,K] * B[Npad,K]^T, hi/lo split, f32 acc
// tile 128x128, K-chunk 64, 3-stage cp.async pipeline, 512 threads (16 warps 4x4,
// warp tile 32x32). MODE 0: in-proj epilogue; MODE 1: plain f32 store.
// ============================================================================
#define STAGE_BYTES 65536        // 4 tiles x 16KB (Ahi Alo Bhi Blo)

template<int MODE>
__global__ __launch_bounds__(512, 1)
void mma_gemm(const __nv_bfloat16* __restrict__ Ahi, const __nv_bfloat16* __restrict__ Alo,
              const __nv_bfloat16* __restrict__ Bhi, const __nv_bfloat16* __restrict__ Blo,
              int K, float* __restrict__ out, const float* __restrict__ dt_bias)
{
    extern __shared__ char smem[];
    const uint32_t sb = smem_u32(smem);
    const int tid = threadIdx.x;
    const int wid = tid >> 5;
    const int lane = tid & 31;
    const int row0 = blockIdx.y * 128;
    const int col0 = blockIdx.x * 128;
    const int NC = K / 64;

    const int wm = wid >> 2;          // 0..3 : warp row   (32 rows)
    const int wn = wid & 3;           // 0..3 : warp col   (32 cols)

    float acc[2][4][4];               // [mt][nj][reg]
    #pragma unroll
    for (int i = 0; i < 2; i++)
        #pragma unroll
        for (int j = 0; j < 4; j++)
            #pragma unroll
            for (int r = 0; r < 4; r++) acc[i][j][r] = 0.f;

    // ldmatrix lane addressing
    const int grp = lane >> 3;        // 0..3
    const int wit = lane & 7;         // 0..7
    const int a_r = wit + (grp & 1) * 8;
    const int a_c = (grp >> 1) * 16;
    const int b_r = wit + (grp >> 1) * 8;
    const int b_c = (grp & 1) * 16;

    // prologue: stages 0,1
    #pragma unroll
    for (int i = 0; i < 2; i++) {
        uint32_t stb = sb + i * STAGE_BYTES;
        load_tile(stb,         Ahi, row0, K, i * 64, tid);
        load_tile(stb + 16384, Alo, row0, K, i * 64, tid);
        load_tile(stb + 32768, Bhi, col0, K, i * 64, tid);
        load_tile(stb + 49152, Blo, col0, K, i * 64, tid);
        CP_COMMIT();
    }

    for (int i = 0; i < NC; i++) {
        const int s = i % 3;
        CP_WAIT1();
        __syncthreads();

        if (i + 2 < NC) {
            int s2 = (i + 2) % 3;
            uint32_t stb = sb + s2 * STAGE_BYTES;
            load_tile(stb,         Ahi, row0, K, (i + 2) * 64, tid);
            load_tile(stb + 16384, Alo, row0, K, (i + 2) * 64, tid);
            load_tile(stb + 32768, Bhi, col0, K, (i + 2) * 64, tid);
            load_tile(stb + 49152, Blo, col0, K, (i + 2) * 64, tid);
            CP_COMMIT();
        }

        const uint32_t sAh = sb + s * STAGE_BYTES;
        const uint32_t sAl = sAh + 16384;
        const uint32_t sBh = sAh + 32768;
        const uint32_t sBl = sAh + 49152;

        #pragma unroll
        for (int ks = 0; ks < 4; ks++) {
            const int kb = ks * 32;   // byte offset of this k16 within 128B row

            uint32_t ah[2][4], al[2][4];
            #pragma unroll
            for (int mt = 0; mt < 2; mt++) {
                int r = wm * 32 + mt * 16 + a_r;
                ldmat_x4(tile_addr(sAh, r, kb + a_c),
                         ah[mt][0], ah[mt][1], ah[mt][2], ah[mt][3]);
                ldmat_x4(tile_addr(sAl, r, kb + a_c),
                         al[mt][0], al[mt][1], al[mt][2], al[mt][3]);
            }
            uint32_t bh[4][2], bl[4][2];
            #pragma unroll
            for (int np = 0; np < 2; np++) {   // n-pair: covers n8 tiles 2np, 2np+1
                int r = wn * 32 + np * 16 + b_r;
                uint32_t t0, t1, t2, t3;
                ldmat_x4(tile_addr(sBh, r, kb + b_c), t0, t1, t2, t3);
                bh[2*np][0] = t0; bh[2*np][1] = t1;
                bh[2*np+1][0] = t2; bh[2*np+1][1] = t3;
                ldmat_x4(tile_addr(sBl, r, kb + b_c), t0, t1, t2, t3);
                bl[2*np][0] = t0; bl[2*np][1] = t1;
                bl[2*np+1][0] = t2; bl[2*np+1][1] = t3;
            }

            #pragma unroll
            for (int mt = 0; mt < 2; mt++)
                #pragma unroll
                for (int nj = 0; nj < 4; nj++) {
                    mma_bf16(acc[mt][nj], ah[mt][0], ah[mt][1], ah[mt][2], ah[mt][3],
                             bh[nj][0], bh[nj][1]);
                    mma_bf16(acc[mt][nj], ah[mt][0], ah[mt][1], ah[mt][2], ah[mt][3],
                             bl[nj][0], bl[nj][1]);
                    mma_bf16(acc[mt][nj], al[mt][0], al[mt][1], al[mt][2], al[mt][3],
                             bh[nj][0], bh[nj][1]);
                }
        }
        __syncthreads();
    }

    // epilogue: direct global stores (each 4-lane quad covers a 32B sector)
    #pragma unroll
    for (int mt = 0; mt < 2; mt++) {
        #pragma unroll
        for (int nj = 0; nj < 4; nj++) {
            int m = row0 + wm * 32 + mt * 16 + (lane >> 2);
            int n = col0 + wn * 32 + nj * 8 + (lane & 3) * 2;
            #pragma unroll
            for (int half = 0; half < 2; half++) {
                int mm = m + half * 8;
                float v0 = acc[mt][nj][half * 2 + 0];
                float v1 = acc[mt][nj][half * 2 + 1];
                if (MODE == 1) {
                    out[(size_t)mm * DMODEL + n]     = v0;
                    out[(size_t)mm * DMODEL + n + 1] = v1;
                } else {
                    #pragma unroll
                    for (int e = 0; e < 2; e++) {
                        int nn = n + e;
                        float v = e ? v1 : v0;
                        if (nn < DINNER) {
                            g_z[(size_t)mm * DINNER + nn] = v;
                        } else if (nn < DINNER + CONVDIM) {
                            g_xBC[(size_t)mm * CONVDIM + (nn - DINNER)] = v;
                        } else if (nn < DPROJ) {
                            int h = nn - (DINNER + CONVDIM);
                            g_dt[(size_t)mm * NHEADS + h] =
                                softplus_f(v + dt_bias[h]);
                        }
                    }
                }
            }
        }
    }
}

// ============================================================================
// hi/lo split kernels
// ============================================================================
__global__ void split_plain(const float* __restrict__ src,
                            __nv_bfloat16* __restrict__ hi,
                            __nv_bfloat16* __restrict__ lo, int n)
{
    int i = blockIdx.x * blockDim.x + threadIdx.x;
    if (i >= n) return;
    float x = src[i];
    __nv_bfloat16 h = __float2bfloat16(x);
    hi[i] = h;
    lo[i] = __float2bfloat16(x - __bfloat162float(h));
}

__global__ void split_w1_pad(const float* __restrict__ W)
{
    int i = blockIdx.x * blockDim.x + threadIdx.x;   // over NPAD1*DMODEL
    if (i >= NPAD1 * DMODEL) return;
    int r = i / DMODEL;
    float x = (r < DPROJ) ? W[(size_t)r * DMODEL + (i - r * DMODEL)] : 0.f;
    __nv_bfloat16 h = __float2bfloat16(x);
    g_W1hi[i] = h;
    g_W1lo[i] = __float2bfloat16(x - __bfloat162float(h));
}

// ============================================================================
// Causal depthwise conv + SiLU + split
// ============================================================================
__global__ void conv_silu_kernel(const float* __restrict__ conv_w,
                                 const float* __restrict__ conv_b)
{
    const int row = blockIdx.x;
    const int b = row / SEQ;
    const int l = row - b * SEQ;
    for (int ch = threadIdx.x; ch < CONVDIM; ch += blockDim.x) {
        float acc = conv_b[ch];
        #pragma unroll
        for (int j = 0; j < DCONV; j++) {
            int ls = l - (DCONV - 1) + j;
            if (ls >= 0)
                acc += conv_w[ch * DCONV + j] *
                       g_xBC[(size_t)(b * SEQ + ls) * CONVDIM + ch];
        }
        float v = silu_f(acc);
        if (ch < DINNER) {
            int h = ch >> 8;
            g_xh[(size_t)row * DINNER + ch] = v * g_dt[(size_t)row * NHEADS + h];
        } else if (ch < DINNER + DSTATE) {
            g_Bm[(size_t)row * DSTATE + (ch - DINNER)] = v;
        } else {
            g_Cm[(size_t)row * DSTATE + (ch - DINNER - DSTATE)] = v;
        }
    }
}

// ============================================================================
// Per-chunk states
// ============================================================================
__global__ void chunk_states_kernel(const float* __restrict__ log_A)
{
    const int id = blockIdx.x;
    const int b = id >> 9;
    const int rem = id & 511;
    const int c = rem >> 3;
    const int h = rem & 7;
    const float a = -expf(log_A[h]);

    __shared__ float Bs[CHUNKL][DSTATE];
    const int t = threadIdx.x;
    for (int i = t; i < CHUNKL * DSTATE; i += 256)
        Bs[i >> 4][i & 15] =
            g_Bm[(size_t)(b * SEQ + c * CHUNKL + (i >> 4)) * DSTATE + (i & 15)];
    __syncthreads();

    float acc[DSTATE];
    #pragma unroll
    for (int n = 0; n < DSTATE; n++) acc[n] = 0.f;

    const int p = t;
    for (int s = 0; s < CHUNKL; s++) {
        float xv = g_xh[(size_t)(b * SEQ + c * CHUNKL + s) * DINNER + h * HEADDIM + p];
        float w = expf(a * (float)(CHUNKL - 1 - s)) * xv;
        #pragma unroll
        for (int n = 0; n < DSTATE; n++) acc[n] += Bs[s][n] * w;
    }
    size_t base = ((size_t)id * HEADDIM + p) * DSTATE;
    #pragma unroll
    for (int n = 0; n < DSTATE; n++) g_states[base + n] = acc[n];
}

// ============================================================================
// Inter-chunk scan
// ============================================================================
__global__ void state_scan_kernel(const float* __restrict__ log_A)
{
    const int gid = blockIdx.x * blockDim.x + threadIdx.x;
    const int b = gid >> 15;
    const int r = gid & 32767;
    const int h = r >> 12;
    const float a = -expf(log_A[h]);
    const float d = expf(a * (float)CHUNKL);
    float P = 0.f;
    for (int c = 0; c < NCHUNK; c++) {
        size_t off = (size_t)(b * NCHUNK + c) * 32768 + r;
        g_Pst[off] = P;
        P = d * P + g_states[off];
    }
}

// ============================================================================
// SSD Y kernel
// ============================================================================
__global__ void ssd_y_kernel(const float* __restrict__ log_A,
                             const float* __restrict__ D_skip)
{
    extern __shared__ float sh[];
    float* Bs = sh;
    float* Cs = sh + 1024;
    float* G  = sh + 2048;
    float* xs = sh + 2048 + 4096;

    const int id = blockIdx.x;
    const int b = id >> 9;
    const int rem = id & 511;
    const int c = rem >> 3;
    const int h = rem & 7;
    const float a = -expf(log_A[h]);
    const int t = threadIdx.x;
    const int rowbase = b * SEQ + c * CHUNKL;

    for (int i = t; i < CHUNKL * DSTATE; i += 256) {
        size_t gi = (size_t)(rowbase + (i >> 4)) * DSTATE + (i & 15);
        Bs[i] = g_Bm[gi];
        Cs[i] = g_Cm[gi];
    }
    for (int i = t; i < CHUNKL * HEADDIM; i += 256) {
        int s = i >> 8, p = i & 255;
        xs[i] = g_xh[(size_t)(rowbase + s) * DINNER + h * HEADDIM + p];
    }
    __syncthreads();

    for (int e = t * 16; e < t * 16 + 16; e++) {
        int tt = e >> 6, ss = e & 63;
        float val = 0.f;
        if (ss <= tt) {
            float dot = 0.f;
            #pragma unroll
            for (int n = 0; n < DSTATE; n++) dot += Cs[tt * 16 + n] * Bs[ss * 16 + n];
            val = expf(a * (float)(tt - ss)) * dot;
        }
        G[e] = val;
    }
    __syncthreads();

    const int p = t;
    float Preg[DSTATE];
    size_t pbase = ((size_t)id * HEADDIM + p) * DSTATE;
    #pragma unroll
    for (int n = 0; n < DSTATE; n++) Preg[n] = g_Pst[pbase + n];
    const float dsk = D_skip[h];

    for (int tt = 0; tt < CHUNKL; tt++) {
        float acc = 0.f;
        const float* Gr = &G[tt * 64];
        for (int ss = 0; ss <= tt; ss++) acc += Gr[ss] * xs[ss * 256 + p];
        float offv = 0.f;
        #pragma unroll
        for (int n = 0; n < DSTATE; n++) offv += Cs[tt * 16 + n] * Preg[n];
        float y = acc + expf(a * (float)(tt + 1)) * offv + dsk * xs[tt * 256 + p];
        g_Y[(size_t)(rowbase + tt) * DINNER + h * HEADDIM + p] = y;
    }
}

// ============================================================================
// Gate + RMS norm; emits bf16 hi/lo for GEMM2
// ============================================================================
__global__ void rms_gate_kernel(const float* __restrict__ norm_w)
{
    const int row = blockIdx.x;
    const int t = threadIdx.x;
    float v[8];
    float ss = 0.f;
    #pragma unroll
    for (int k = 0; k < 8; k++) {
        int ch = k * 256 + t;
        float Yv = g_Y[(size_t)row * DINNER + ch];
        float zv = g_z[(size_t)row * DINNER + ch];
        float val = Yv * silu_f(zv);
        v[k] = val;
        ss += val * val;
    }
    __shared__ float red[256];
    red[t] = ss;
    __syncthreads();
    for (int st = 128; st > 0; st >>= 1) {
        if (t < st) red[t] += red[t + st];
        __syncthreads();
    }
    float inv = rsqrtf(red[0] / (float)DINNER + 1e-5f);
    #pragma unroll
    for (int k = 0; k < 8; k++) {
        int ch = k * 256 + t;
        float val = v[k] * inv * norm_w[ch];
        __nv_bfloat16 hv = __float2bfloat16(val);
        g_Yhi[(size_t)row * DINNER + ch] = hv;
        g_Ylo[(size_t)row * DINNER + ch] =
            __float2bfloat16(val - __bfloat162float(hv));
    }
}

// ============================================================================
// Launch
// ============================================================================
extern "C" void kernel_launch(void* const* d_in, const int* in_sizes, int n_in,
                              void* d_out, int out_size)
{
    const float* input   = (const float*)d_in[0];
    const float* W_in    = (const float*)d_in[1];
    const float* conv_w  = (const float*)d_in[2];
    const float* conv_b  = (const float*)d_in[3];
    const float* dt_bias = (const float*)d_in[4];
    const float* log_A   = (const float*)d_in[5];
    const float* D_skip  = (const float*)d_in[6];
    const float* norm_w  = (const float*)d_in[7];
    const float* W_out   = (const float*)d_in[8];
    float* out = (float*)d_out;

    (void)in_sizes; (void)n_in; (void)out_size;

    const int GSMEM = 3 * STAGE_BYTES;               // 196608 B
    const int SMEM_Y = (1024 + 1024 + 4096 + 16384) * 4;
    cudaFuncSetAttribute(mma_gemm<0>, cudaFuncAttributeMaxDynamicSharedMemorySize, GSMEM);
    cudaFuncSetAttribute(mma_gemm<1>, cudaFuncAttributeMaxDynamicSharedMemorySize, GSMEM);
    cudaFuncSetAttribute(ssd_y_kernel, cudaFuncAttributeMaxDynamicSharedMemorySize, SMEM_Y);

    __nv_bfloat16 *Xhi, *Xlo, *W2hi, *W2lo, *Yhi, *Ylo, *W1hi, *W1lo;
    cudaGetSymbolAddress((void**)&Xhi,  g_Xhi);
    cudaGetSymbolAddress((void**)&Xlo,  g_Xlo);
    cudaGetSymbolAddress((void**)&W2hi, g_W2hi);
    cudaGetSymbolAddress((void**)&W2lo, g_W2lo);
    cudaGetSymbolAddress((void**)&Yhi,  g_Yhi);
    cudaGetSymbolAddress((void**)&Ylo,  g_Ylo);
    cudaGetSymbolAddress((void**)&W1hi, g_W1hi);
    cudaGetSymbolAddress((void**)&W1lo, g_W1lo);

    // splits
    {
        int n = NROWS * DMODEL;
        split_plain<<<(n + 255) / 256, 256>>>(input, Xhi, Xlo, n);
    }
    split_w1_pad<<<(NPAD1 * DMODEL + 255) / 256, 256>>>(W_in);
    {
        int n = DMODEL * DINNER;
        split_plain<<<(n + 255) / 256, 256>>>(W_out, W2hi, W2lo, n);
    }

    // 1) in-projection (mma.sync bf16 split)
    mma_gemm<0><<<dim3(NPAD1 / 128, NROWS / 128), 512, GSMEM>>>(
        Xhi, Xlo, W1hi, W1lo, DMODEL, nullptr, dt_bias);

    // 2) conv + silu + split
    conv_silu_kernel<<<NROWS, 256>>>(conv_w, conv_b);

    // 3) per-chunk states
    chunk_states_kernel<<<BATCH * NCHUNK * NHEADS, 256>>>(log_A);

    // 4) inter-chunk scan
    state_scan_kernel<<<(BATCH * NHEADS * HEADDIM * DSTATE) / 256, 256>>>(log_A);

    // 5) Y
    ssd_y_kernel<<<BATCH * NCHUNK * NHEADS, 256, SMEM_Y>>>(log_A, D_skip);

    // 6) gate + RMS norm (emits bf16 hi/lo)
    rms_gate_kernel<<<NROWS, 256>>>(norm_w);

    // 7) out-projection (mma.sync bf16 split)
    mma_gemm<1><<<dim3(DMODEL / 128, NROWS / 128), 512, GSMEM>>>(
        Yhi, Ylo, W2hi, W2lo, DINNER, out, nullptr);
}